// round 14
// baseline (speedup 1.0000x reference)
#include <cuda_runtime.h>
#include <cuda_fp16.h>
#include <cuda_bf16.h>

#define N_USERS 100000
#define N_ITEMS 50000
#define N_NODES 150000
#define KDIM    64
#define N_EDGES 2000000
#define BATCH   4096
#define NEG_SLOPE 0.01f
#define EPSV    1e-12f

#define SCAN_ELEMS 4096
#define SCAN_BLOCKS ((N_NODES + SCAN_ELEMS - 1) / SCAN_ELEMS)   // 37

// ---- HMMA update constants ----
#define UPD_NODES 128
#define UPD_BLOCKS ((N_NODES + UPD_NODES - 1) / UPD_NODES)   // 1172
#define AS_STRIDE 136
#define SM_BIAS 0
#define SM_A    512
#define SM_B    (512 + 128 * AS_STRIDE * 2)
#define UPD_SMEM (SM_B + 64 * AS_STRIDE * 2)

typedef unsigned u32;

__device__ __forceinline__ void mma16816(float* d, const u32* a, const u32* b) {
    asm volatile(
        "mma.sync.aligned.m16n8k16.row.col.f32.bf16.bf16.f32 "
        "{%0,%1,%2,%3}, {%4,%5,%6,%7}, {%8,%9}, {%0,%1,%2,%3};"
        : "+f"(d[0]), "+f"(d[1]), "+f"(d[2]), "+f"(d[3])
        : "r"(a[0]), "r"(a[1]), "r"(a[2]), "r"(a[3]), "r"(b[0]), "r"(b[1]));
}

// ---------------- scratch ----------------------------------------------------
__device__ float   g_X[(size_t)N_NODES * KDIM];
__device__ float   g_Y[(size_t)N_NODES * KDIM];
__device__ __half2 g_Xh[(size_t)N_NODES * KDIM / 2];
__device__ __half2 g_Yh[(size_t)N_NODES * KDIM / 2];
__device__ float   g_S[(size_t)N_NODES * KDIM];
__device__ float   g_wsum[N_NODES];
__device__ int     g_cnt[N_NODES];
__device__ int     g_off[N_NODES + 1];
__device__ int     g_fill[N_NODES];
__device__ int2    g_edge[N_EDGES];
__device__ int     g_part[SCAN_BLOCKS];

// ---------------- init -------------------------------------------------------
__global__ void k_init(const float* __restrict__ Gu, const float* __restrict__ Gi) {
    int i = blockIdx.x * blockDim.x + threadIdx.x;
    const int total  = N_NODES * KDIM / 4;
    const int usplit = N_USERS * KDIM / 4;
    if (i < N_NODES) g_cnt[i] = 0;
    if (i >= total) return;
    float4 v = (i < usplit) ? ((const float4*)Gu)[i] : ((const float4*)Gi)[i - usplit];
    ((float4*)g_X)[i] = v;
    g_Xh[i * 2]     = __floats2half2_rn(v.x, v.y);
    g_Xh[i * 2 + 1] = __floats2half2_rn(v.z, v.w);
}

// ---------------- CSR build --------------------------------------------------
__global__ void k_hist(const int* __restrict__ dst) {
    int t = blockIdx.x * blockDim.x + threadIdx.x;
    int e = t * 8;
    if (e + 7 < N_EDGES) {
        int4 a4 = *(const int4*)&dst[e];
        int4 b4 = *(const int4*)&dst[e + 4];
        atomicAdd(&g_cnt[a4.x], 1);
        atomicAdd(&g_cnt[a4.y], 1);
        atomicAdd(&g_cnt[a4.z], 1);
        atomicAdd(&g_cnt[a4.w], 1);
        atomicAdd(&g_cnt[b4.x], 1);
        atomicAdd(&g_cnt[b4.y], 1);
        atomicAdd(&g_cnt[b4.z], 1);
        atomicAdd(&g_cnt[b4.w], 1);
    } else {
        for (int i = e; i < N_EDGES; i++) atomicAdd(&g_cnt[dst[i]], 1);
    }
}

__global__ void __launch_bounds__(1024) k_part() {
    __shared__ int red[32];
    int tid = threadIdx.x;
    int base = blockIdx.x * SCAN_ELEMS + tid * 4;
    int s = 0;
#pragma unroll
    for (int j = 0; j < 4; j++) {
        int g = base + j;
        s += (g < N_NODES) ? g_cnt[g] : 0;
    }
#pragma unroll
    for (int o = 16; o; o >>= 1) s += __shfl_xor_sync(0xffffffffu, s, o);
    if ((tid & 31) == 0) red[tid >> 5] = s;
    __syncthreads();
    if (tid < 32) {
        int v = red[tid];
#pragma unroll
        for (int o = 16; o; o >>= 1) v += __shfl_xor_sync(0xffffffffu, v, o);
        if (tid == 0) g_part[blockIdx.x] = v;
    }
}

// block prefix computed inline (reads <=37 partials), no separate scan kernel
__global__ void __launch_bounds__(1024) k_scanfinal() {
    __shared__ int wsm[33];
    __shared__ int s_prefix;
    int tid = threadIdx.x;
    int lane = tid & 31, wid = tid >> 5;
    int base = blockIdx.x * SCAN_ELEMS + tid * 4;
    int v[4];
    int t = 0;
#pragma unroll
    for (int j = 0; j < 4; j++) {
        int g = base + j;
        v[j] = (g < N_NODES) ? g_cnt[g] : 0;
        t += v[j];
    }
    // warp 1, lane 0..: compute exclusive prefix of partials for this block
    if (tid == 32) {
        int pfx = 0;
        for (int b = 0; b < (int)blockIdx.x; b++) pfx += g_part[b];
        s_prefix = pfx;
    }
    if (tid == 33 && blockIdx.x == SCAN_BLOCKS - 1) {
        int tot = 0;
        for (int b = 0; b < SCAN_BLOCKS; b++) tot += g_part[b];
        g_off[N_NODES] = tot;
    }
    int inc = t;
#pragma unroll
    for (int o = 1; o < 32; o <<= 1) {
        int u = __shfl_up_sync(0xffffffffu, inc, o);
        if (lane >= o) inc += u;
    }
    if (lane == 31) wsm[wid] = inc;
    __syncthreads();
    if (wid == 0) {
        int w = wsm[lane];
        int wi = w;
#pragma unroll
        for (int o = 1; o < 32; o <<= 1) {
            int u = __shfl_up_sync(0xffffffffu, wi, o);
            if (lane >= o) wi += u;
        }
        wsm[lane] = wi - w;
    }
    __syncthreads();
    int excl = s_prefix + wsm[wid] + inc - t;
#pragma unroll
    for (int j = 0; j < 4; j++) {
        int g = base + j;
        if (g < N_NODES) { g_off[g] = excl; g_fill[g] = excl; }
        excl += v[j];
    }
}

__global__ void k_fill(const int* __restrict__ src, const int* __restrict__ dst,
                       const float* __restrict__ ew) {
    int t = blockIdx.x * blockDim.x + threadIdx.x;
    int e = t * 8;
    if (e + 7 < N_EDGES) {
        int4   sa = *(const int4*)&src[e];
        int4   sb = *(const int4*)&src[e + 4];
        int4   da = *(const int4*)&dst[e];
        int4   db = *(const int4*)&dst[e + 4];
        float4 wa = *(const float4*)&ew[e];
        float4 wb = *(const float4*)&ew[e + 4];
        int p0 = atomicAdd(&g_fill[da.x], 1);
        int p1 = atomicAdd(&g_fill[da.y], 1);
        int p2 = atomicAdd(&g_fill[da.z], 1);
        int p3 = atomicAdd(&g_fill[da.w], 1);
        int p4 = atomicAdd(&g_fill[db.x], 1);
        int p5 = atomicAdd(&g_fill[db.y], 1);
        int p6 = atomicAdd(&g_fill[db.z], 1);
        int p7 = atomicAdd(&g_fill[db.w], 1);
        g_edge[p0] = make_int2(sa.x, __float_as_int(wa.x));
        g_edge[p1] = make_int2(sa.y, __float_as_int(wa.y));
        g_edge[p2] = make_int2(sa.z, __float_as_int(wa.z));
        g_edge[p3] = make_int2(sa.w, __float_as_int(wa.w));
        g_edge[p4] = make_int2(sb.x, __float_as_int(wb.x));
        g_edge[p5] = make_int2(sb.y, __float_as_int(wb.y));
        g_edge[p6] = make_int2(sb.z, __float_as_int(wb.z));
        g_edge[p7] = make_int2(sb.w, __float_as_int(wb.w));
    } else {
        for (int i = e; i < N_EDGES; i++) {
            int p = atomicAdd(&g_fill[dst[i]], 1);
            g_edge[p] = make_int2(src[i], __float_as_int(ew[i]));
        }
    }
}

// ---------------- per-layer gather over fp16 mirror (unroll 8) ---------------
__global__ void k_gather(int insel) {
    const __half2* __restrict__ X = insel ? g_Yh : g_Xh;
    int gthr = blockIdx.x * blockDim.x + threadIdx.x;
    int n = gthr >> 5;
    if (n >= N_NODES) return;
    int lane = threadIdx.x & 31;
    int b = g_off[n], e = g_off[n + 1];
    float ax = 0.0f, ay = 0.0f, wa = 0.0f;
    int i = b;
    for (; i + 7 < e; i += 8) {
        int2 E[8];
#pragma unroll
        for (int q = 0; q < 8; q++) E[q] = g_edge[i + q];
        float2 v[8];
#pragma unroll
        for (int q = 0; q < 8; q++)
            v[q] = __half22float2(X[(size_t)E[q].x * 32 + lane]);
#pragma unroll
        for (int q = 0; q < 8; q++) {
            float w = __int_as_float(E[q].y);
            ax += w * v[q].x;
            ay += w * v[q].y;
            wa += w;
        }
    }
    for (; i + 3 < e; i += 4) {
        int2 E0 = g_edge[i];
        int2 E1 = g_edge[i + 1];
        int2 E2 = g_edge[i + 2];
        int2 E3 = g_edge[i + 3];
        float2 v0 = __half22float2(X[(size_t)E0.x * 32 + lane]);
        float2 v1 = __half22float2(X[(size_t)E1.x * 32 + lane]);
        float2 v2 = __half22float2(X[(size_t)E2.x * 32 + lane]);
        float2 v3 = __half22float2(X[(size_t)E3.x * 32 + lane]);
        float w0 = __int_as_float(E0.y), w1 = __int_as_float(E1.y);
        float w2 = __int_as_float(E2.y), w3 = __int_as_float(E3.y);
        ax += w0 * v0.x + w1 * v1.x + w2 * v2.x + w3 * v3.x;
        ay += w0 * v0.y + w1 * v1.y + w2 * v2.y + w3 * v3.y;
        wa += w0 + w1 + w2 + w3;
    }
    for (; i < e; i++) {
        int2 E0 = g_edge[i];
        float w0 = __int_as_float(E0.y);
        float2 v0 = __half22float2(X[(size_t)E0.x * 32 + lane]);
        ax += w0 * v0.x;
        ay += w0 * v0.y;
        wa += w0;
    }
    *(float2*)&g_S[(size_t)n * KDIM + lane * 2] = make_float2(ax, ay);
    if (insel == 0 && lane == 0) g_wsum[n] = wa;
}

// ---------------- per-layer update via mma.sync bf16 HMMA --------------------
__global__ void __launch_bounds__(128) k_update(
    const float* __restrict__ W1, const float* __restrict__ b1,
    const float* __restrict__ W2, const float* __restrict__ b2,
    int l) {
    extern __shared__ char smem[];
    float* sBias = (float*)(smem + SM_BIAS);
    __nv_bfloat16* As = (__nv_bfloat16*)(smem + SM_A);
    __nv_bfloat16* Bs = (__nv_bfloat16*)(smem + SM_B);

    const float* __restrict__ Xin = (l & 1) ? g_Y : g_X;
    float* __restrict__ Yout      = (l & 1) ? g_X : g_Y;
    __half2* __restrict__ Yh      = (l & 1) ? g_Xh : g_Yh;
    const float* W1l = W1 + l * 4096;
    const float* W2l = W2 + l * 4096;

    int tid = threadIdx.x;
    int node0 = blockIdx.x * UPD_NODES;

    {
        int t16 = tid & 15, grp = tid >> 4;
        int c = t16 * 4;
#pragma unroll
        for (int m = 0; m < 16; m++) {
            int nl = grp * 16 + m;
            int n = node0 + nl;
            float4 a4, b4;
            if (n < N_NODES) {
                float4 sv = *(const float4*)&g_S[(size_t)n * KDIM + c];
                float4 xv = *(const float4*)&Xin[(size_t)n * KDIM + c];
                a4 = make_float4(sv.x + xv.x, sv.y + xv.y, sv.z + xv.z, sv.w + xv.w);
                b4 = make_float4(sv.x * xv.x, sv.y * xv.y, sv.z * xv.z, sv.w * xv.w);
            } else {
                a4 = make_float4(0.f, 0.f, 0.f, 0.f);
                b4 = a4;
            }
            __nv_bfloat162* row = (__nv_bfloat162*)&As[nl * AS_STRIDE];
            row[(c >> 1)]      = __floats2bfloat162_rn(a4.x, a4.y);
            row[(c >> 1) + 1]  = __floats2bfloat162_rn(a4.z, a4.w);
            row[(c >> 1) + 32] = __floats2bfloat162_rn(b4.x, b4.y);
            row[(c >> 1) + 33] = __floats2bfloat162_rn(b4.z, b4.w);
        }
    }

#pragma unroll
    for (int p = 0; p < 8; p++) {
        int j = p * 128 + tid;
        int k = j >> 4;
        int n0 = (j & 15) * 4;
        float4 w = ((const float4*)W1l)[j];
        Bs[(n0 + 0) * AS_STRIDE + k] = __float2bfloat16(w.x);
        Bs[(n0 + 1) * AS_STRIDE + k] = __float2bfloat16(w.y);
        Bs[(n0 + 2) * AS_STRIDE + k] = __float2bfloat16(w.z);
        Bs[(n0 + 3) * AS_STRIDE + k] = __float2bfloat16(w.w);
        float4 w2 = ((const float4*)W2l)[j];
        Bs[(n0 + 0) * AS_STRIDE + 64 + k] = __float2bfloat16(w2.x);
        Bs[(n0 + 1) * AS_STRIDE + 64 + k] = __float2bfloat16(w2.y);
        Bs[(n0 + 2) * AS_STRIDE + 64 + k] = __float2bfloat16(w2.z);
        Bs[(n0 + 3) * AS_STRIDE + 64 + k] = __float2bfloat16(w2.w);
    }

    sBias[tid] = (tid < 64) ? b1[l * 64 + tid] : b2[l * 64 + (tid - 64)];
    __syncthreads();

    int warp = tid >> 5, lane = tid & 31;
    int g = lane >> 2;
    int c0 = (lane & 3) * 2;
    int m_base = warp * 32;

    float acc[2][8][4];
#pragma unroll
    for (int mt = 0; mt < 2; mt++)
#pragma unroll
        for (int nt = 0; nt < 8; nt++)
#pragma unroll
            for (int q = 0; q < 4; q++) acc[mt][nt][q] = 0.0f;

#pragma unroll
    for (int kt = 0; kt < 8; kt++) {
        int kb = kt * 16;
        u32 a[2][4];
#pragma unroll
        for (int mt = 0; mt < 2; mt++) {
            int r0 = m_base + mt * 16 + g;
            a[mt][0] = *(const u32*)&As[r0 * AS_STRIDE + kb + c0];
            a[mt][1] = *(const u32*)&As[(r0 + 8) * AS_STRIDE + kb + c0];
            a[mt][2] = *(const u32*)&As[r0 * AS_STRIDE + kb + 8 + c0];
            a[mt][3] = *(const u32*)&As[(r0 + 8) * AS_STRIDE + kb + 8 + c0];
        }
#pragma unroll
        for (int nt = 0; nt < 8; nt++) {
            int nrow = nt * 8 + g;
            u32 b[2];
            b[0] = *(const u32*)&Bs[nrow * AS_STRIDE + kb + c0];
            b[1] = *(const u32*)&Bs[nrow * AS_STRIDE + kb + 8 + c0];
            mma16816(acc[0][nt], a[0], b);
            mma16816(acc[1][nt], a[1], b);
        }
    }

#pragma unroll
    for (int mt = 0; mt < 2; mt++) {
        int rl = node0 + m_base + mt * 16 + g;
        int rh = rl + 8;
        float wsl = (rl < N_NODES) ? g_wsum[rl] : 0.0f;
        float wsh = (rh < N_NODES) ? g_wsum[rh] : 0.0f;
        float ssl = 0.0f, ssh = 0.0f;
#pragma unroll
        for (int nt = 0; nt < 8; nt++) {
            int cA = nt * 8 + c0;
            float b1a = sBias[cA], b1b = sBias[cA + 1];
            float b2a = sBias[64 + cA], b2b = sBias[64 + cA + 1];
            float v0 = acc[mt][nt][0] + (wsl + 1.0f) * b1a + wsl * b2a;
            float v1 = acc[mt][nt][1] + (wsl + 1.0f) * b1b + wsl * b2b;
            float v2 = acc[mt][nt][2] + (wsh + 1.0f) * b1a + wsh * b2a;
            float v3 = acc[mt][nt][3] + (wsh + 1.0f) * b1b + wsh * b2b;
            v0 = v0 > 0.0f ? v0 : NEG_SLOPE * v0;
            v1 = v1 > 0.0f ? v1 : NEG_SLOPE * v1;
            v2 = v2 > 0.0f ? v2 : NEG_SLOPE * v2;
            v3 = v3 > 0.0f ? v3 : NEG_SLOPE * v3;
            acc[mt][nt][0] = v0; acc[mt][nt][1] = v1;
            acc[mt][nt][2] = v2; acc[mt][nt][3] = v3;
            ssl += v0 * v0 + v1 * v1;
            ssh += v2 * v2 + v3 * v3;
        }
        ssl += __shfl_xor_sync(0xffffffffu, ssl, 1);
        ssl += __shfl_xor_sync(0xffffffffu, ssl, 2);
        ssh += __shfl_xor_sync(0xffffffffu, ssh, 1);
        ssh += __shfl_xor_sync(0xffffffffu, ssh, 2);
        float invl = 1.0f / fmaxf(sqrtf(ssl), EPSV);
        float invh = 1.0f / fmaxf(sqrtf(ssh), EPSV);
#pragma unroll
        for (int nt = 0; nt < 8; nt++) {
            int cA = nt * 8 + c0;
            if (rl < N_NODES) {
                float y0 = acc[mt][nt][0] * invl;
                float y1 = acc[mt][nt][1] * invl;
                *(float2*)&Yout[(size_t)rl * KDIM + cA] = make_float2(y0, y1);
                Yh[(size_t)rl * 32 + (cA >> 1)] = __floats2half2_rn(y0, y1);
            }
            if (rh < N_NODES) {
                float y2 = acc[mt][nt][2] * invh;
                float y3 = acc[mt][nt][3] * invh;
                *(float2*)&Yout[(size_t)rh * KDIM + cA] = make_float2(y2, y3);
                Yh[(size_t)rh * 32 + (cA >> 1)] = __floats2half2_rn(y2, y3);
            }
        }
    }
}

// ---------------- incremental batch dot --------------------------------------
__global__ void k_dot(const int* __restrict__ user, const int* __restrict__ pos,
                      float* __restrict__ out, int sel, int first) {
    const float* __restrict__ X = sel ? g_Y : g_X;
    int gthr = blockIdx.x * blockDim.x + threadIdx.x;
    int w = gthr >> 5;
    if (w >= BATCH) return;
    int lane = threadIdx.x & 31;
    int u  = user[w];
    int it = pos[w];
    float2 a = *(const float2*)&X[(size_t)u * KDIM + lane * 2];
    float2 b = *(const float2*)&X[((size_t)N_USERS + it) * KDIM + lane * 2];
    float d = a.x * b.x + a.y * b.y;
    d += __shfl_xor_sync(0xffffffffu, d, 16);
    d += __shfl_xor_sync(0xffffffffu, d, 8);
    d += __shfl_xor_sync(0xffffffffu, d, 4);
    d += __shfl_xor_sync(0xffffffffu, d, 2);
    d += __shfl_xor_sync(0xffffffffu, d, 1);
    if (lane == 0) out[w] = first ? d : out[w] + d;
}

// ---------------- launch -------------------------------------------------------
extern "C" void kernel_launch(void* const* d_in, const int* in_sizes, int n_in,
                              void* d_out, int out_size) {
    const float* Gu   = (const float*)d_in[0];
    const float* Gi   = (const float*)d_in[1];
    const float* W1   = (const float*)d_in[2];
    const float* b1   = (const float*)d_in[3];
    const float* W2   = (const float*)d_in[4];
    const float* b2   = (const float*)d_in[5];
    const float* ew   = (const float*)d_in[6];
    const int*   esrc = (const int*)d_in[7];
    const int*   edst = (const int*)d_in[8];
    const int*   user = (const int*)d_in[9];
    const int*   pos  = (const int*)d_in[10];
    float* out = (float*)d_out;

    cudaFuncSetAttribute(k_update, cudaFuncAttributeMaxDynamicSharedMemorySize,
                         UPD_SMEM);

    const int TB = 256;
    k_init<<<(N_NODES * KDIM / 4 + TB - 1) / TB, TB>>>(Gu, Gi);
    k_hist<<<(N_EDGES / 8 + TB - 1) / TB, TB>>>(edst);
    k_part<<<SCAN_BLOCKS, 1024>>>();
    k_scanfinal<<<SCAN_BLOCKS, 1024>>>();
    k_fill<<<(N_EDGES / 8 + TB - 1) / TB, TB>>>(esrc, edst, ew);

    k_dot<<<(BATCH * 32 + TB - 1) / TB, TB>>>(user, pos, out, /*sel=*/0, /*first=*/1);

    for (int l = 0; l < 3; l++) {
        int insel  = l & 1;
        int outsel = insel ^ 1;
        k_gather<<<(N_NODES * 32 + TB - 1) / TB, TB>>>(insel);
        k_update<<<UPD_BLOCKS, 128, UPD_SMEM>>>(W1, b1, W2, b2, l);
        k_dot<<<(BATCH * 32 + TB - 1) / TB, TB>>>(user, pos, out, outsel, /*first=*/0);
    }
}

// round 15
// speedup vs baseline: 1.0349x; 1.0349x over previous
#include <cuda_runtime.h>
#include <cuda_fp16.h>
#include <cuda_bf16.h>

#define N_USERS 100000
#define N_ITEMS 50000
#define N_NODES 150000
#define KDIM    64
#define N_EDGES 2000000
#define BATCH   4096
#define NEG_SLOPE 0.01f
#define EPSV    1e-12f

#define SCAN_ELEMS 4096
#define SCAN_BLOCKS ((N_NODES + SCAN_ELEMS - 1) / SCAN_ELEMS)   // 37

// ---- HMMA update constants ----
#define UPD_NODES 128
#define UPD_BLOCKS ((N_NODES + UPD_NODES - 1) / UPD_NODES)   // 1172
#define AS_STRIDE 136
#define SM_BIAS 0
#define SM_A    512
#define SM_B    (512 + 128 * AS_STRIDE * 2)
#define UPD_SMEM (SM_B + 64 * AS_STRIDE * 2)

typedef unsigned u32;

__device__ __forceinline__ void mma16816(float* d, const u32* a, const u32* b) {
    asm volatile(
        "mma.sync.aligned.m16n8k16.row.col.f32.bf16.bf16.f32 "
        "{%0,%1,%2,%3}, {%4,%5,%6,%7}, {%8,%9}, {%0,%1,%2,%3};"
        : "+f"(d[0]), "+f"(d[1]), "+f"(d[2]), "+f"(d[3])
        : "r"(a[0]), "r"(a[1]), "r"(a[2]), "r"(a[3]), "r"(b[0]), "r"(b[1]));
}

// ---------------- scratch ----------------------------------------------------
__device__ float   g_X[(size_t)N_NODES * KDIM];
__device__ float   g_Y[(size_t)N_NODES * KDIM];
__device__ __half2 g_Xh[(size_t)N_NODES * KDIM / 2];
__device__ __half2 g_Yh[(size_t)N_NODES * KDIM / 2];
__device__ __half2 g_Sh[(size_t)N_NODES * KDIM / 2];   // fp16 gathered sums
__device__ float   g_wsum[N_NODES];
__device__ int     g_cnt[N_NODES];
__device__ int     g_off[N_NODES + 1];
__device__ int     g_fill[N_NODES];
__device__ int2    g_edge[N_EDGES];
__device__ int     g_part[SCAN_BLOCKS];

// ---------------- init -------------------------------------------------------
__global__ void k_init(const float* __restrict__ Gu, const float* __restrict__ Gi) {
    int i = blockIdx.x * blockDim.x + threadIdx.x;
    const int total  = N_NODES * KDIM / 4;
    const int usplit = N_USERS * KDIM / 4;
    if (i < N_NODES) g_cnt[i] = 0;
    if (i >= total) return;
    float4 v = (i < usplit) ? ((const float4*)Gu)[i] : ((const float4*)Gi)[i - usplit];
    ((float4*)g_X)[i] = v;
    g_Xh[i * 2]     = __floats2half2_rn(v.x, v.y);
    g_Xh[i * 2 + 1] = __floats2half2_rn(v.z, v.w);
}

// ---------------- CSR build --------------------------------------------------
__global__ void k_hist(const int* __restrict__ dst) {
    int t = blockIdx.x * blockDim.x + threadIdx.x;
    int e = t * 8;
    if (e + 7 < N_EDGES) {
        int4 a4 = *(const int4*)&dst[e];
        int4 b4 = *(const int4*)&dst[e + 4];
        atomicAdd(&g_cnt[a4.x], 1);
        atomicAdd(&g_cnt[a4.y], 1);
        atomicAdd(&g_cnt[a4.z], 1);
        atomicAdd(&g_cnt[a4.w], 1);
        atomicAdd(&g_cnt[b4.x], 1);
        atomicAdd(&g_cnt[b4.y], 1);
        atomicAdd(&g_cnt[b4.z], 1);
        atomicAdd(&g_cnt[b4.w], 1);
    } else {
        for (int i = e; i < N_EDGES; i++) atomicAdd(&g_cnt[dst[i]], 1);
    }
}

__global__ void __launch_bounds__(1024) k_part() {
    __shared__ int red[32];
    int tid = threadIdx.x;
    int base = blockIdx.x * SCAN_ELEMS + tid * 4;
    int s = 0;
#pragma unroll
    for (int j = 0; j < 4; j++) {
        int g = base + j;
        s += (g < N_NODES) ? g_cnt[g] : 0;
    }
#pragma unroll
    for (int o = 16; o; o >>= 1) s += __shfl_xor_sync(0xffffffffu, s, o);
    if ((tid & 31) == 0) red[tid >> 5] = s;
    __syncthreads();
    if (tid < 32) {
        int v = red[tid];
#pragma unroll
        for (int o = 16; o; o >>= 1) v += __shfl_xor_sync(0xffffffffu, v, o);
        if (tid == 0) g_part[blockIdx.x] = v;
    }
}

__global__ void __launch_bounds__(1024) k_scanfinal() {
    __shared__ int wsm[33];
    __shared__ int s_prefix;
    int tid = threadIdx.x;
    int lane = tid & 31, wid = tid >> 5;
    int base = blockIdx.x * SCAN_ELEMS + tid * 4;
    int v[4];
    int t = 0;
#pragma unroll
    for (int j = 0; j < 4; j++) {
        int g = base + j;
        v[j] = (g < N_NODES) ? g_cnt[g] : 0;
        t += v[j];
    }
    if (tid == 32) {
        int pfx = 0;
        for (int b = 0; b < (int)blockIdx.x; b++) pfx += g_part[b];
        s_prefix = pfx;
    }
    if (tid == 33 && blockIdx.x == SCAN_BLOCKS - 1) {
        int tot = 0;
        for (int b = 0; b < SCAN_BLOCKS; b++) tot += g_part[b];
        g_off[N_NODES] = tot;
    }
    int inc = t;
#pragma unroll
    for (int o = 1; o < 32; o <<= 1) {
        int u = __shfl_up_sync(0xffffffffu, inc, o);
        if (lane >= o) inc += u;
    }
    if (lane == 31) wsm[wid] = inc;
    __syncthreads();
    if (wid == 0) {
        int w = wsm[lane];
        int wi = w;
#pragma unroll
        for (int o = 1; o < 32; o <<= 1) {
            int u = __shfl_up_sync(0xffffffffu, wi, o);
            if (lane >= o) wi += u;
        }
        wsm[lane] = wi - w;
    }
    __syncthreads();
    int excl = s_prefix + wsm[wid] + inc - t;
#pragma unroll
    for (int j = 0; j < 4; j++) {
        int g = base + j;
        if (g < N_NODES) { g_off[g] = excl; g_fill[g] = excl; }
        excl += v[j];
    }
}

__global__ void k_fill(const int* __restrict__ src, const int* __restrict__ dst,
                       const float* __restrict__ ew) {
    int t = blockIdx.x * blockDim.x + threadIdx.x;
    int e = t * 8;
    if (e + 7 < N_EDGES) {
        int4   sa = *(const int4*)&src[e];
        int4   sb = *(const int4*)&src[e + 4];
        int4   da = *(const int4*)&dst[e];
        int4   db = *(const int4*)&dst[e + 4];
        float4 wa = *(const float4*)&ew[e];
        float4 wb = *(const float4*)&ew[e + 4];
        int p0 = atomicAdd(&g_fill[da.x], 1);
        int p1 = atomicAdd(&g_fill[da.y], 1);
        int p2 = atomicAdd(&g_fill[da.z], 1);
        int p3 = atomicAdd(&g_fill[da.w], 1);
        int p4 = atomicAdd(&g_fill[db.x], 1);
        int p5 = atomicAdd(&g_fill[db.y], 1);
        int p6 = atomicAdd(&g_fill[db.z], 1);
        int p7 = atomicAdd(&g_fill[db.w], 1);
        g_edge[p0] = make_int2(sa.x, __float_as_int(wa.x));
        g_edge[p1] = make_int2(sa.y, __float_as_int(wa.y));
        g_edge[p2] = make_int2(sa.z, __float_as_int(wa.z));
        g_edge[p3] = make_int2(sa.w, __float_as_int(wa.w));
        g_edge[p4] = make_int2(sb.x, __float_as_int(wb.x));
        g_edge[p5] = make_int2(sb.y, __float_as_int(wb.y));
        g_edge[p6] = make_int2(sb.z, __float_as_int(wb.z));
        g_edge[p7] = make_int2(sb.w, __float_as_int(wb.w));
    } else {
        for (int i = e; i < N_EDGES; i++) {
            int p = atomicAdd(&g_fill[dst[i]], 1);
            g_edge[p] = make_int2(src[i], __float_as_int(ew[i]));
        }
    }
}

// ---------------- per-layer gather over fp16 mirror (unroll 4) ---------------
__global__ void k_gather(int insel) {
    const __half2* __restrict__ X = insel ? g_Yh : g_Xh;
    int gthr = blockIdx.x * blockDim.x + threadIdx.x;
    int n = gthr >> 5;
    if (n >= N_NODES) return;
    int lane = threadIdx.x & 31;
    int b = g_off[n], e = g_off[n + 1];
    float ax = 0.0f, ay = 0.0f, wa = 0.0f;
    int i = b;
    for (; i + 3 < e; i += 4) {
        int2 E0 = g_edge[i];
        int2 E1 = g_edge[i + 1];
        int2 E2 = g_edge[i + 2];
        int2 E3 = g_edge[i + 3];
        float2 v0 = __half22float2(X[(size_t)E0.x * 32 + lane]);
        float2 v1 = __half22float2(X[(size_t)E1.x * 32 + lane]);
        float2 v2 = __half22float2(X[(size_t)E2.x * 32 + lane]);
        float2 v3 = __half22float2(X[(size_t)E3.x * 32 + lane]);
        float w0 = __int_as_float(E0.y), w1 = __int_as_float(E1.y);
        float w2 = __int_as_float(E2.y), w3 = __int_as_float(E3.y);
        ax += w0 * v0.x + w1 * v1.x + w2 * v2.x + w3 * v3.x;
        ay += w0 * v0.y + w1 * v1.y + w2 * v2.y + w3 * v3.y;
        wa += w0 + w1 + w2 + w3;
    }
    for (; i < e; i++) {
        int2 E0 = g_edge[i];
        float w0 = __int_as_float(E0.y);
        float2 v0 = __half22float2(X[(size_t)E0.x * 32 + lane]);
        ax += w0 * v0.x;
        ay += w0 * v0.y;
        wa += w0;
    }
    g_Sh[(size_t)n * 32 + lane] = __floats2half2_rn(ax, ay);
    if (insel == 0 && lane == 0) g_wsum[n] = wa;
}

// ---------------- per-layer update via mma.sync bf16 HMMA --------------------
__global__ void __launch_bounds__(128) k_update(
    const float* __restrict__ W1, const float* __restrict__ b1,
    const float* __restrict__ W2, const float* __restrict__ b2,
    int l) {
    extern __shared__ char smem[];
    float* sBias = (float*)(smem + SM_BIAS);
    __nv_bfloat16* As = (__nv_bfloat16*)(smem + SM_A);
    __nv_bfloat16* Bs = (__nv_bfloat16*)(smem + SM_B);

    const float* __restrict__ Xin = (l & 1) ? g_Y : g_X;
    float* __restrict__ Yout      = (l & 1) ? g_X : g_Y;
    __half2* __restrict__ Yh      = (l & 1) ? g_Xh : g_Yh;
    const float* W1l = W1 + l * 4096;
    const float* W2l = W2 + l * 4096;

    int tid = threadIdx.x;
    int node0 = blockIdx.x * UPD_NODES;

    {
        int t16 = tid & 15, grp = tid >> 4;
        int c = t16 * 4;
#pragma unroll
        for (int m = 0; m < 16; m++) {
            int nl = grp * 16 + m;
            int n = node0 + nl;
            float4 a4, b4;
            if (n < N_NODES) {
                float2 s01 = __half22float2(g_Sh[(size_t)n * 32 + (c >> 1)]);
                float2 s23 = __half22float2(g_Sh[(size_t)n * 32 + (c >> 1) + 1]);
                float4 xv = *(const float4*)&Xin[(size_t)n * KDIM + c];
                a4 = make_float4(s01.x + xv.x, s01.y + xv.y, s23.x + xv.z, s23.y + xv.w);
                b4 = make_float4(s01.x * xv.x, s01.y * xv.y, s23.x * xv.z, s23.y * xv.w);
            } else {
                a4 = make_float4(0.f, 0.f, 0.f, 0.f);
                b4 = a4;
            }
            __nv_bfloat162* row = (__nv_bfloat162*)&As[nl * AS_STRIDE];
            row[(c >> 1)]      = __floats2bfloat162_rn(a4.x, a4.y);
            row[(c >> 1) + 1]  = __floats2bfloat162_rn(a4.z, a4.w);
            row[(c >> 1) + 32] = __floats2bfloat162_rn(b4.x, b4.y);
            row[(c >> 1) + 33] = __floats2bfloat162_rn(b4.z, b4.w);
        }
    }

#pragma unroll
    for (int p = 0; p < 8; p++) {
        int j = p * 128 + tid;
        int k = j >> 4;
        int n0 = (j & 15) * 4;
        float4 w = ((const float4*)W1l)[j];
        Bs[(n0 + 0) * AS_STRIDE + k] = __float2bfloat16(w.x);
        Bs[(n0 + 1) * AS_STRIDE + k] = __float2bfloat16(w.y);
        Bs[(n0 + 2) * AS_STRIDE + k] = __float2bfloat16(w.z);
        Bs[(n0 + 3) * AS_STRIDE + k] = __float2bfloat16(w.w);
        float4 w2 = ((const float4*)W2l)[j];
        Bs[(n0 + 0) * AS_STRIDE + 64 + k] = __float2bfloat16(w2.x);
        Bs[(n0 + 1) * AS_STRIDE + 64 + k] = __float2bfloat16(w2.y);
        Bs[(n0 + 2) * AS_STRIDE + 64 + k] = __float2bfloat16(w2.z);
        Bs[(n0 + 3) * AS_STRIDE + 64 + k] = __float2bfloat16(w2.w);
    }

    sBias[tid] = (tid < 64) ? b1[l * 64 + tid] : b2[l * 64 + (tid - 64)];
    __syncthreads();

    int warp = tid >> 5, lane = tid & 31;
    int g = lane >> 2;
    int c0 = (lane & 3) * 2;
    int m_base = warp * 32;

    float acc[2][8][4];
#pragma unroll
    for (int mt = 0; mt < 2; mt++)
#pragma unroll
        for (int nt = 0; nt < 8; nt++)
#pragma unroll
            for (int q = 0; q < 4; q++) acc[mt][nt][q] = 0.0f;

#pragma unroll
    for (int kt = 0; kt < 8; kt++) {
        int kb = kt * 16;
        u32 a[2][4];
#pragma unroll
        for (int mt = 0; mt < 2; mt++) {
            int r0 = m_base + mt * 16 + g;
            a[mt][0] = *(const u32*)&As[r0 * AS_STRIDE + kb + c0];
            a[mt][1] = *(const u32*)&As[(r0 + 8) * AS_STRIDE + kb + c0];
            a[mt][2] = *(const u32*)&As[r0 * AS_STRIDE + kb + 8 + c0];
            a[mt][3] = *(const u32*)&As[(r0 + 8) * AS_STRIDE + kb + 8 + c0];
        }
#pragma unroll
        for (int nt = 0; nt < 8; nt++) {
            int nrow = nt * 8 + g;
            u32 b[2];
            b[0] = *(const u32*)&Bs[nrow * AS_STRIDE + kb + c0];
            b[1] = *(const u32*)&Bs[nrow * AS_STRIDE + kb + 8 + c0];
            mma16816(acc[0][nt], a[0], b);
            mma16816(acc[1][nt], a[1], b);
        }
    }

#pragma unroll
    for (int mt = 0; mt < 2; mt++) {
        int rl = node0 + m_base + mt * 16 + g;
        int rh = rl + 8;
        float wsl = (rl < N_NODES) ? g_wsum[rl] : 0.0f;
        float wsh = (rh < N_NODES) ? g_wsum[rh] : 0.0f;
        float ssl = 0.0f, ssh = 0.0f;
#pragma unroll
        for (int nt = 0; nt < 8; nt++) {
            int cA = nt * 8 + c0;
            float b1a = sBias[cA], b1b = sBias[cA + 1];
            float b2a = sBias[64 + cA], b2b = sBias[64 + cA + 1];
            float v0 = acc[mt][nt][0] + (wsl + 1.0f) * b1a + wsl * b2a;
            float v1 = acc[mt][nt][1] + (wsl + 1.0f) * b1b + wsl * b2b;
            float v2 = acc[mt][nt][2] + (wsh + 1.0f) * b1a + wsh * b2a;
            float v3 = acc[mt][nt][3] + (wsh + 1.0f) * b1b + wsh * b2b;
            v0 = v0 > 0.0f ? v0 : NEG_SLOPE * v0;
            v1 = v1 > 0.0f ? v1 : NEG_SLOPE * v1;
            v2 = v2 > 0.0f ? v2 : NEG_SLOPE * v2;
            v3 = v3 > 0.0f ? v3 : NEG_SLOPE * v3;
            acc[mt][nt][0] = v0; acc[mt][nt][1] = v1;
            acc[mt][nt][2] = v2; acc[mt][nt][3] = v3;
            ssl += v0 * v0 + v1 * v1;
            ssh += v2 * v2 + v3 * v3;
        }
        ssl += __shfl_xor_sync(0xffffffffu, ssl, 1);
        ssl += __shfl_xor_sync(0xffffffffu, ssl, 2);
        ssh += __shfl_xor_sync(0xffffffffu, ssh, 1);
        ssh += __shfl_xor_sync(0xffffffffu, ssh, 2);
        float invl = 1.0f / fmaxf(sqrtf(ssl), EPSV);
        float invh = 1.0f / fmaxf(sqrtf(ssh), EPSV);
#pragma unroll
        for (int nt = 0; nt < 8; nt++) {
            int cA = nt * 8 + c0;
            if (rl < N_NODES) {
                float y0 = acc[mt][nt][0] * invl;
                float y1 = acc[mt][nt][1] * invl;
                *(float2*)&Yout[(size_t)rl * KDIM + cA] = make_float2(y0, y1);
                Yh[(size_t)rl * 32 + (cA >> 1)] = __floats2half2_rn(y0, y1);
            }
            if (rh < N_NODES) {
                float y2 = acc[mt][nt][2] * invh;
                float y3 = acc[mt][nt][3] * invh;
                *(float2*)&Yout[(size_t)rh * KDIM + cA] = make_float2(y2, y3);
                Yh[(size_t)rh * 32 + (cA >> 1)] = __floats2half2_rn(y2, y3);
            }
        }
    }
}

// ---------------- incremental batch dot --------------------------------------
__global__ void k_dot(const int* __restrict__ user, const int* __restrict__ pos,
                      float* __restrict__ out, int sel, int first) {
    const float* __restrict__ X = sel ? g_Y : g_X;
    int gthr = blockIdx.x * blockDim.x + threadIdx.x;
    int w = gthr >> 5;
    if (w >= BATCH) return;
    int lane = threadIdx.x & 31;
    int u  = user[w];
    int it = pos[w];
    float2 a = *(const float2*)&X[(size_t)u * KDIM + lane * 2];
    float2 b = *(const float2*)&X[((size_t)N_USERS + it) * KDIM + lane * 2];
    float d = a.x * b.x + a.y * b.y;
    d += __shfl_xor_sync(0xffffffffu, d, 16);
    d += __shfl_xor_sync(0xffffffffu, d, 8);
    d += __shfl_xor_sync(0xffffffffu, d, 4);
    d += __shfl_xor_sync(0xffffffffu, d, 2);
    d += __shfl_xor_sync(0xffffffffu, d, 1);
    if (lane == 0) out[w] = first ? d : out[w] + d;
}

// ---------------- launch -------------------------------------------------------
extern "C" void kernel_launch(void* const* d_in, const int* in_sizes, int n_in,
                              void* d_out, int out_size) {
    const float* Gu   = (const float*)d_in[0];
    const float* Gi   = (const float*)d_in[1];
    const float* W1   = (const float*)d_in[2];
    const float* b1   = (const float*)d_in[3];
    const float* W2   = (const float*)d_in[4];
    const float* b2   = (const float*)d_in[5];
    const float* ew   = (const float*)d_in[6];
    const int*   esrc = (const int*)d_in[7];
    const int*   edst = (const int*)d_in[8];
    const int*   user = (const int*)d_in[9];
    const int*   pos  = (const int*)d_in[10];
    float* out = (float*)d_out;

    cudaFuncSetAttribute(k_update, cudaFuncAttributeMaxDynamicSharedMemorySize,
                         UPD_SMEM);

    const int TB = 256;
    k_init<<<(N_NODES * KDIM / 4 + TB - 1) / TB, TB>>>(Gu, Gi);
    k_hist<<<(N_EDGES / 8 + TB - 1) / TB, TB>>>(edst);
    k_part<<<SCAN_BLOCKS, 1024>>>();
    k_scanfinal<<<SCAN_BLOCKS, 1024>>>();
    k_fill<<<(N_EDGES / 8 + TB - 1) / TB, TB>>>(esrc, edst, ew);

    k_dot<<<(BATCH * 32 + TB - 1) / TB, TB>>>(user, pos, out, /*sel=*/0, /*first=*/1);

    for (int l = 0; l < 3; l++) {
        int insel  = l & 1;
        int outsel = insel ^ 1;
        k_gather<<<(N_NODES * 32 + TB - 1) / TB, TB>>>(insel);
        k_update<<<UPD_BLOCKS, 128, UPD_SMEM>>>(W1, b1, W2, b2, l);
        k_dot<<<(BATCH * 32 + TB - 1) / TB, TB>>>(user, pos, out, outsel, /*first=*/0);
    }
}